// round 10
// baseline (speedup 1.0000x reference)
#include <cuda_runtime.h>
#include <cstdint>

#define BB 32
#define TT 2048
#define HH 1024
#define UU 1024
#define BT (BB*TT)

// score GEMM tiling
#define TM 128
#define TN 128
#define KC 32
#define NCHUNK (HH/KC)    // 32
#define NBLK (UU/TN)      // 8
#define STAGES 3

// SMEM pitches (floats) — padded for conflict-free fragment access
#define APITCH 36         // 32 + 4 pad
#define BPITCH 136        // 128 + 8 pad
#define ABYTES (TM*APITCH*4)       // 18432
#define BBYTES (KC*BPITCH*4)       // 17408
#define BUFBYTES (ABYTES+BBYTES)   // 35840
#define SM_DEC (STAGES*BUFBYTES)   // 107520
#define SM_VA  (SM_DEC + TN*4)
#define SM_RED (SM_VA + TN*4)
#define SMEM_TOTAL (SM_RED + TM*4*4)   // 110592

// Scratch
__device__ float g_dec_proj[BB*UU];
__device__ float g_score_part[NBLK][BT];
__device__ float g_score[BT];
__device__ float g_ctx_part[16][BB*HH];

__device__ __forceinline__ float tanh_fast(float x) {
    float y; asm("tanh.approx.f32 %0, %1;" : "=f"(y) : "f"(x)); return y;
}
__device__ __forceinline__ uint32_t smem_u32(const void* p) {
    uint32_t a;
    asm("{ .reg .u64 t; cvta.to.shared.u64 t, %1; cvt.u32.u64 %0, t; }" : "=r"(a) : "l"(p));
    return a;
}
__device__ __forceinline__ void cpasync16(uint32_t dst, const void* src) {
    asm volatile("cp.async.cg.shared.global [%0], [%1], 16;" :: "r"(dst), "l"(src));
}
__device__ __forceinline__ void ldsm4(uint32_t* r, uint32_t addr) {
    asm volatile("ldmatrix.sync.aligned.m8n8.x4.shared.b16 {%0,%1,%2,%3}, [%4];"
                 : "=r"(r[0]), "=r"(r[1]), "=r"(r[2]), "=r"(r[3]) : "r"(addr));
}
__device__ __forceinline__ void mma_tf32(float* d, const uint32_t* a,
                                         uint32_t b0, uint32_t b1) {
    asm volatile(
        "mma.sync.aligned.m16n8k8.row.col.f32.tf32.tf32.f32 "
        "{%0,%1,%2,%3}, {%4,%5,%6,%7}, {%8,%9}, {%0,%1,%2,%3};"
        : "+f"(d[0]), "+f"(d[1]), "+f"(d[2]), "+f"(d[3])
        : "r"(a[0]), "r"(a[1]), "r"(a[2]), "r"(a[3]), "r"(b0), "r"(b1));
}

// ---------------------------------------------------------------------------
// dec_proj[b,u] = dec_hidden[b,:] @ Wa.  grid (B, 4), 256 thr.
// ---------------------------------------------------------------------------
__global__ __launch_bounds__(256) void k_dec_proj(const float* __restrict__ dec,
                                                  const float* __restrict__ Wa) {
    __shared__ float dh[HH];
    int b = blockIdx.x;
    int u = blockIdx.y * 256 + threadIdx.x;
    for (int i = threadIdx.x; i < HH; i += 256) dh[i] = dec[b * HH + i];
    __syncthreads();
    float acc = 0.f;
    #pragma unroll 16
    for (int h = 0; h < HH; ++h) acc += dh[h] * Wa[(size_t)h * UU + u];
    g_dec_proj[b * UU + u] = acc;
}

// ---------------------------------------------------------------------------
// Dominant kernel: tf32 mma.sync GEMM (enc @ Ua) with fused tanh/Va epilogue.
// 3-stage cp.async pipeline; A fragments via ldmatrix.x4.
// grid = (NBLK=8, BT/TM=512), block = 256 (8 warps of 64x32 tiles).
// ---------------------------------------------------------------------------
__global__ void __launch_bounds__(256, 2)
k_score_mma(const float* __restrict__ enc,
            const float* __restrict__ Ua,
            const float* __restrict__ Va) {
    extern __shared__ __align__(16) char smem[];
    const uint32_t sb = smem_u32(smem);
    const int tid  = threadIdx.x;
    const int lane = tid & 31;
    const int wid  = tid >> 5;
    const int g    = lane >> 2;       // groupID
    const int tc   = lane & 3;        // threadID_in_group
    const int Mw   = wid & 1;         // warp M row (0/1)
    const int Nw   = wid >> 1;        // warp N col (0..3)

    const int u0 = blockIdx.x * TN;
    const int r0 = blockIdx.y * TM;
    const int b  = blockIdx.y >> 4;   // r0 / TT

    float* s_dec = (float*)(smem + SM_DEC);
    float* s_va  = (float*)(smem + SM_VA);
    float* s_red = (float*)(smem + SM_RED);
    if (tid < TN) {
        s_dec[tid] = g_dec_proj[b * UU + u0 + tid];
        s_va[tid]  = Va[u0 + tid];
    }

    const float* Ag = enc + (size_t)r0 * HH;
    const float* Bg = Ua + u0;

    // load indexing (per thread)
    const int a_row = tid >> 3, a_k4 = tid & 7;     // A staging
    const int b_k   = tid >> 5, b_n4 = tid & 31;    // B staging

    float d[4][4][4] = {};   // [Mtile][Ntile][reg]

    // ---- prologue: stage chunks 0 and 1 ----
    #pragma unroll
    for (int st = 0; st < STAGES - 1; ++st) {
        const uint32_t ab = sb + st * BUFBYTES;
        const int k0 = st * KC;
        #pragma unroll
        for (int j = 0; j < 4; ++j) {
            int row = a_row + 32 * j;
            cpasync16(ab + row * (APITCH*4) + a_k4 * 16,
                      Ag + (size_t)row * HH + k0 + a_k4 * 4);
        }
        #pragma unroll
        for (int j = 0; j < 4; ++j) {
            int k = b_k + 8 * j;
            cpasync16(ab + ABYTES + k * (BPITCH*4) + b_n4 * 16,
                      Bg + (size_t)(k0 + k) * UU + b_n4 * 4);
        }
        asm volatile("cp.async.commit_group;" ::: "memory");
    }

    // per-lane bases (bytes, within a buffer)
    // A via ldmatrix: row = lane&15 within the 16-row tile, k-half = lane>>4
    const uint32_t aLdsm = (uint32_t)((Mw * 64 + (lane & 15)) * (APITCH*4)
                                      + (lane >> 4) * 16);
    const uint32_t bLane = (uint32_t)(tc * (BPITCH*4) + (Nw * 32 + g) * 4);

    int cur = 0, nxt = STAGES - 1;
    for (int c = 0; c < NCHUNK; ++c) {
        if (c + 1 < NCHUNK)
            asm volatile("cp.async.wait_group 1;" ::: "memory");
        else
            asm volatile("cp.async.wait_group 0;" ::: "memory");
        __syncthreads();

        // issue stage c+2 (overwrites buffer read in chunk c-1; safe after sync)
        if (c + STAGES - 1 < NCHUNK) {
            const uint32_t ab = sb + nxt * BUFBYTES;
            const int k0 = (c + STAGES - 1) * KC;
            #pragma unroll
            for (int j = 0; j < 4; ++j) {
                int row = a_row + 32 * j;
                cpasync16(ab + row * (APITCH*4) + a_k4 * 16,
                          Ag + (size_t)row * HH + k0 + a_k4 * 4);
            }
            #pragma unroll
            for (int j = 0; j < 4; ++j) {
                int k = b_k + 8 * j;
                cpasync16(ab + ABYTES + k * (BPITCH*4) + b_n4 * 16,
                          Bg + (size_t)(k0 + k) * UU + b_n4 * 4);
            }
            asm volatile("cp.async.commit_group;" ::: "memory");
        }

        // ---- compute chunk c from buffer cur ----
        const uint32_t bufo = cur * BUFBYTES;
        const uint32_t aB = sb + bufo + aLdsm;
        #pragma unroll
        for (int s = 0; s < 4; ++s) {
            uint32_t a[4][4];
            #pragma unroll
            for (int i = 0; i < 4; ++i)
                ldsm4(a[i], aB + i * 16 * (APITCH*4) + s * 32);
            #pragma unroll
            for (int jn = 0; jn < 4; ++jn) {
                const uint32_t* q = (const uint32_t*)(smem +
                    bufo + ABYTES + bLane + s * 8 * (BPITCH*4) + jn * 32);
                uint32_t b0 = q[0];
                uint32_t b1 = q[4 * BPITCH];
                #pragma unroll
                for (int i = 0; i < 4; ++i)
                    mma_tf32(d[i][jn], a[i], b0, b1);
            }
        }
        cur = (cur == STAGES - 1) ? 0 : cur + 1;
        nxt = (nxt == STAGES - 1) ? 0 : nxt + 1;
    }

    // ---- fused epilogue: tanh(d + dec)*Va, reduce over u ----
    float rowacc[4][2] = {};
    #pragma unroll
    for (int i = 0; i < 4; ++i)
        #pragma unroll
        for (int jn = 0; jn < 4; ++jn)
            #pragma unroll
            for (int r = 0; r < 4; ++r) {
                int ul = Nw * 32 + jn * 8 + tc * 2 + (r & 1);
                float v = tanh_fast(d[i][jn][r] + s_dec[ul]) * s_va[ul];
                rowacc[i][r >> 1] += v;
            }
    #pragma unroll
    for (int i = 0; i < 4; ++i)
        #pragma unroll
        for (int h = 0; h < 2; ++h) {
            float v = rowacc[i][h];
            v += __shfl_xor_sync(0xffffffffu, v, 1);
            v += __shfl_xor_sync(0xffffffffu, v, 2);
            rowacc[i][h] = v;
        }
    if (tc == 0) {
        #pragma unroll
        for (int i = 0; i < 4; ++i)
            #pragma unroll
            for (int h = 0; h < 2; ++h) {
                int m = Mw * 64 + i * 16 + h * 8 + g;
                s_red[m * 4 + Nw] = rowacc[i][h];
            }
    }
    __syncthreads();
    if (tid < TM) {
        float s = s_red[tid * 4] + s_red[tid * 4 + 1]
                + s_red[tid * 4 + 2] + s_red[tid * 4 + 3];
        g_score_part[blockIdx.x][r0 + tid] = s;
    }
}

// ---------------------------------------------------------------------------
// Softmax over T (sums the 8 N-block partials). grid (B), 256 thr.
// ---------------------------------------------------------------------------
__global__ __launch_bounds__(256) void k_softmax() {
    int b = blockIdx.x, tid = threadIdx.x;
    __shared__ float sm[256];
    float* sc = g_score + b * TT;

    float m = -1e30f;
    for (int t = tid; t < TT; t += 256) {
        float v = 0.f;
        #pragma unroll
        for (int p = 0; p < NBLK; ++p) v += g_score_part[p][b * TT + t];
        sc[t] = v;
        m = fmaxf(m, v);
    }
    sm[tid] = m; __syncthreads();
    for (int s = 128; s > 0; s >>= 1) {
        if (tid < s) sm[tid] = fmaxf(sm[tid], sm[tid + s]);
        __syncthreads();
    }
    m = sm[0]; __syncthreads();

    float sum = 0.f;
    for (int t = tid; t < TT; t += 256) {
        float e = __expf(sc[t] - m);
        sc[t] = e; sum += e;
    }
    sm[tid] = sum; __syncthreads();
    for (int s = 128; s > 0; s >>= 1) {
        if (tid < s) sm[tid] += sm[tid + s];
        __syncthreads();
    }
    float inv = 1.f / sm[0];
    for (int t = tid; t < TT; t += 256) sc[t] *= inv;
}

// ---------------------------------------------------------------------------
// Context: grid (B, H/256, 16), block 256. Each block: 128 t's for 256 h's.
// ---------------------------------------------------------------------------
__global__ __launch_bounds__(256) void k_ctx_part(const float* __restrict__ enc) {
    int b = blockIdx.x, hc = blockIdx.y, tc = blockIdx.z;
    int h = hc * 256 + threadIdx.x;
    int t0 = tc * 128;
    __shared__ float s_al[128];
    if (threadIdx.x < 128) s_al[threadIdx.x] = g_score[b * TT + t0 + threadIdx.x];
    __syncthreads();
    float acc = 0.f;
    const float* e = enc + ((size_t)b * TT + t0) * HH + h;
    #pragma unroll 16
    for (int t = 0; t < 128; ++t) acc += s_al[t] * e[(size_t)t * HH];
    g_ctx_part[tc][b * HH + h] = acc;
}

__global__ __launch_bounds__(256) void k_ctx_final(float* __restrict__ out) {
    int idx = blockIdx.x * 256 + threadIdx.x;
    float s = 0.f;
    #pragma unroll
    for (int p = 0; p < 16; ++p) s += g_ctx_part[p][idx];
    out[idx] = s;
}

// ---------------------------------------------------------------------------
extern "C" void kernel_launch(void* const* d_in, const int* in_sizes, int n_in,
                              void* d_out, int out_size) {
    const float* enc = (const float*)d_in[0];
    const float* dec = (const float*)d_in[1];
    const float* Wa  = (const float*)d_in[2];
    const float* Ua  = (const float*)d_in[3];
    const float* Va  = (const float*)d_in[4];
    float* out = (float*)d_out;

    static int smem_set = 0;
    if (!smem_set) {
        cudaFuncSetAttribute(k_score_mma,
                             cudaFuncAttributeMaxDynamicSharedMemorySize,
                             SMEM_TOTAL);
        smem_set = 1;
    }

    k_dec_proj<<<dim3(BB, 4), 256>>>(dec, Wa);
    k_score_mma<<<dim3(NBLK, BT / TM), 256, SMEM_TOTAL>>>(enc, Ua, Va);
    k_softmax<<<BB, 256>>>();
    k_ctx_part<<<dim3(BB, HH / 256, 16), 256>>>(enc);
    k_ctx_final<<<(BB * HH) / 256, 256>>>(out);
}

// round 11
// speedup vs baseline: 1.2943x; 1.2943x over previous
#include <cuda_runtime.h>
#include <cstdint>

#define BB 32
#define TT 2048
#define HH 1024
#define UU 1024
#define BT (BB*TT)

// score GEMM tiling
#define TM 256
#define TN 128
#define KC 32
#define NCHUNK (HH/KC)    // 32
#define NBLK (UU/TN)      // 8
#define STAGES 3
#define NTHR 512

// SMEM pitches (floats) — padded for conflict-free fragment access
#define APITCH 36         // 32 + 4 pad
#define BPITCH 136        // 128 + 8 pad
#define ABYTES (TM*APITCH*4)       // 36864
#define BBYTES (KC*BPITCH*4)       // 17408
#define BUFBYTES (ABYTES+BBYTES)   // 54272
#define SM_DEC (STAGES*BUFBYTES)   // 162816
#define SM_VA  (SM_DEC + TN*4)
#define SM_RED (SM_VA + TN*4)
#define SMEM_TOTAL (SM_RED + TM*4*4)   // 167936

// Scratch
__device__ float g_dec_proj[BB*UU];
__device__ float g_score_part[NBLK][BT];
__device__ float g_score[BT];
__device__ float g_ctx_part[16][BB*HH];

__device__ __forceinline__ float tanh_fast(float x) {
    float y; asm("tanh.approx.f32 %0, %1;" : "=f"(y) : "f"(x)); return y;
}
__device__ __forceinline__ uint32_t smem_u32(const void* p) {
    uint32_t a;
    asm("{ .reg .u64 t; cvta.to.shared.u64 t, %1; cvt.u32.u64 %0, t; }" : "=r"(a) : "l"(p));
    return a;
}
__device__ __forceinline__ void cpasync16(uint32_t dst, const void* src) {
    asm volatile("cp.async.cg.shared.global [%0], [%1], 16;" :: "r"(dst), "l"(src));
}
__device__ __forceinline__ void mma_tf32(float* d, const uint32_t* a,
                                         uint32_t b0, uint32_t b1) {
    asm volatile(
        "mma.sync.aligned.m16n8k8.row.col.f32.tf32.tf32.f32 "
        "{%0,%1,%2,%3}, {%4,%5,%6,%7}, {%8,%9}, {%0,%1,%2,%3};"
        : "+f"(d[0]), "+f"(d[1]), "+f"(d[2]), "+f"(d[3])
        : "r"(a[0]), "r"(a[1]), "r"(a[2]), "r"(a[3]), "r"(b0), "r"(b1));
}

// ---------------------------------------------------------------------------
// dec_proj[b,u] = dec_hidden[b,:] @ Wa.  grid (B, 4), 256 thr.
// ---------------------------------------------------------------------------
__global__ __launch_bounds__(256) void k_dec_proj(const float* __restrict__ dec,
                                                  const float* __restrict__ Wa) {
    __shared__ float dh[HH];
    int b = blockIdx.x;
    int u = blockIdx.y * 256 + threadIdx.x;
    for (int i = threadIdx.x; i < HH; i += 256) dh[i] = dec[b * HH + i];
    __syncthreads();
    float acc = 0.f;
    #pragma unroll 16
    for (int h = 0; h < HH; ++h) acc += dh[h] * Wa[(size_t)h * UU + u];
    g_dec_proj[b * UU + u] = acc;
}

// ---------------------------------------------------------------------------
// Dominant kernel: tf32 mma.sync GEMM (enc @ Ua) with fused tanh/Va epilogue.
// 3-stage cp.async pipeline; scalar-LDS fragments (conflict-free pitches).
// grid = (NBLK=8, BT/TM=256), block = 512 (16 warps of 64x32 tiles).
// ---------------------------------------------------------------------------
__global__ void __launch_bounds__(NTHR, 1)
k_score_mma(const float* __restrict__ enc,
            const float* __restrict__ Ua,
            const float* __restrict__ Va) {
    extern __shared__ __align__(16) char smem[];
    const uint32_t sb = smem_u32(smem);
    const int tid  = threadIdx.x;
    const int lane = tid & 31;
    const int wid  = tid >> 5;
    const int g    = lane >> 2;       // groupID
    const int tc   = lane & 3;        // threadID_in_group
    const int Mw   = wid & 3;         // warp M row (0..3)
    const int Nw   = wid >> 2;        // warp N col (0..3)

    const int u0 = blockIdx.x * TN;
    const int r0 = blockIdx.y * TM;
    const int b  = blockIdx.y >> 3;   // r0 / TT  (TT/TM = 8)

    float* s_dec = (float*)(smem + SM_DEC);
    float* s_va  = (float*)(smem + SM_VA);
    float* s_red = (float*)(smem + SM_RED);
    if (tid < TN) {
        s_dec[tid] = g_dec_proj[b * UU + u0 + tid];
        s_va[tid]  = Va[u0 + tid];
    }

    const float* Ag = enc + (size_t)r0 * HH;
    const float* Bg = Ua + u0;

    // staging indexing (per thread)
    const int a_row = tid >> 3, a_k4 = tid & 7;     // A: 64 rows per j-step
    const int b_k   = tid >> 5, b_n4 = tid & 31;    // B: 16 k-rows per j-step

    float d[4][4][4] = {};   // [Mtile][Ntile][reg]

    // ---- prologue: stage chunks 0 and 1 ----
    #pragma unroll
    for (int st = 0; st < STAGES - 1; ++st) {
        const uint32_t ab = sb + st * BUFBYTES;
        const int k0 = st * KC;
        #pragma unroll
        for (int j = 0; j < 4; ++j) {
            int row = a_row + 64 * j;
            cpasync16(ab + row * (APITCH*4) + a_k4 * 16,
                      Ag + (size_t)row * HH + k0 + a_k4 * 4);
        }
        #pragma unroll
        for (int j = 0; j < 2; ++j) {
            int k = b_k + 16 * j;
            cpasync16(ab + ABYTES + k * (BPITCH*4) + b_n4 * 16,
                      Bg + (size_t)(k0 + k) * UU + b_n4 * 4);
        }
        asm volatile("cp.async.commit_group;" ::: "memory");
    }

    // per-lane fragment base offsets (bytes, within a buffer)
    const uint32_t aLane = (uint32_t)((Mw * 64 + g) * (APITCH*4) + tc * 4);
    const uint32_t bLane = (uint32_t)(tc * (BPITCH*4) + (Nw * 32 + g) * 4);

    int cur = 0, nxt = STAGES - 1;
    for (int c = 0; c < NCHUNK; ++c) {
        if (c + 1 < NCHUNK)
            asm volatile("cp.async.wait_group 1;" ::: "memory");
        else
            asm volatile("cp.async.wait_group 0;" ::: "memory");
        __syncthreads();

        // issue stage c+2 (overwrites buffer read in chunk c-1; safe after sync)
        if (c + STAGES - 1 < NCHUNK) {
            const uint32_t ab = sb + nxt * BUFBYTES;
            const int k0 = (c + STAGES - 1) * KC;
            #pragma unroll
            for (int j = 0; j < 4; ++j) {
                int row = a_row + 64 * j;
                cpasync16(ab + row * (APITCH*4) + a_k4 * 16,
                          Ag + (size_t)row * HH + k0 + a_k4 * 4);
            }
            #pragma unroll
            for (int j = 0; j < 2; ++j) {
                int k = b_k + 16 * j;
                cpasync16(ab + ABYTES + k * (BPITCH*4) + b_n4 * 16,
                          Bg + (size_t)(k0 + k) * UU + b_n4 * 4);
            }
            asm volatile("cp.async.commit_group;" ::: "memory");
        }

        // ---- compute chunk c from buffer cur ----
        const uint32_t bufo = cur * BUFBYTES;
        #pragma unroll
        for (int s = 0; s < 4; ++s) {
            uint32_t a[4][4];
            #pragma unroll
            for (int i = 0; i < 4; ++i) {
                const uint32_t* p = (const uint32_t*)(smem +
                    bufo + aLane + i * 16 * (APITCH*4) + s * 32);
                a[i][0] = p[0];
                a[i][1] = p[8 * APITCH];
                a[i][2] = p[4];
                a[i][3] = p[8 * APITCH + 4];
            }
            #pragma unroll
            for (int jn = 0; jn < 4; ++jn) {
                const uint32_t* q = (const uint32_t*)(smem +
                    bufo + ABYTES + bLane + s * 8 * (BPITCH*4) + jn * 32);
                uint32_t b0 = q[0];
                uint32_t b1 = q[4 * BPITCH];
                #pragma unroll
                for (int i = 0; i < 4; ++i)
                    mma_tf32(d[i][jn], a[i], b0, b1);
            }
        }
        cur = (cur == STAGES - 1) ? 0 : cur + 1;
        nxt = (nxt == STAGES - 1) ? 0 : nxt + 1;
    }

    // ---- fused epilogue: tanh(d + dec)*Va, reduce over u ----
    float rowacc[4][2] = {};
    #pragma unroll
    for (int i = 0; i < 4; ++i)
        #pragma unroll
        for (int jn = 0; jn < 4; ++jn)
            #pragma unroll
            for (int r = 0; r < 4; ++r) {
                int ul = Nw * 32 + jn * 8 + tc * 2 + (r & 1);
                float v = tanh_fast(d[i][jn][r] + s_dec[ul]) * s_va[ul];
                rowacc[i][r >> 1] += v;
            }
    #pragma unroll
    for (int i = 0; i < 4; ++i)
        #pragma unroll
        for (int h = 0; h < 2; ++h) {
            float v = rowacc[i][h];
            v += __shfl_xor_sync(0xffffffffu, v, 1);
            v += __shfl_xor_sync(0xffffffffu, v, 2);
            rowacc[i][h] = v;
        }
    if (tc == 0) {
        #pragma unroll
        for (int i = 0; i < 4; ++i)
            #pragma unroll
            for (int h = 0; h < 2; ++h) {
                int m = Mw * 64 + i * 16 + h * 8 + g;
                s_red[m * 4 + Nw] = rowacc[i][h];
            }
    }
    __syncthreads();
    if (tid < TM) {
        float s = s_red[tid * 4] + s_red[tid * 4 + 1]
                + s_red[tid * 4 + 2] + s_red[tid * 4 + 3];
        g_score_part[blockIdx.x][r0 + tid] = s;
    }
}

// ---------------------------------------------------------------------------
// Softmax over T (sums the 8 N-block partials). grid (B), 256 thr.
// ---------------------------------------------------------------------------
__global__ __launch_bounds__(256) void k_softmax() {
    int b = blockIdx.x, tid = threadIdx.x;
    __shared__ float sm[256];
    float* sc = g_score + b * TT;

    float m = -1e30f;
    for (int t = tid; t < TT; t += 256) {
        float v = 0.f;
        #pragma unroll
        for (int p = 0; p < NBLK; ++p) v += g_score_part[p][b * TT + t];
        sc[t] = v;
        m = fmaxf(m, v);
    }
    sm[tid] = m; __syncthreads();
    for (int s = 128; s > 0; s >>= 1) {
        if (tid < s) sm[tid] = fmaxf(sm[tid], sm[tid + s]);
        __syncthreads();
    }
    m = sm[0]; __syncthreads();

    float sum = 0.f;
    for (int t = tid; t < TT; t += 256) {
        float e = __expf(sc[t] - m);
        sc[t] = e; sum += e;
    }
    sm[tid] = sum; __syncthreads();
    for (int s = 128; s > 0; s >>= 1) {
        if (tid < s) sm[tid] += sm[tid + s];
        __syncthreads();
    }
    float inv = 1.f / sm[0];
    for (int t = tid; t < TT; t += 256) sc[t] *= inv;
}

// ---------------------------------------------------------------------------
// Context: grid (B, H/256, 16), block 256. Each block: 128 t's for 256 h's.
// ---------------------------------------------------------------------------
__global__ __launch_bounds__(256) void k_ctx_part(const float* __restrict__ enc) {
    int b = blockIdx.x, hc = blockIdx.y, tc = blockIdx.z;
    int h = hc * 256 + threadIdx.x;
    int t0 = tc * 128;
    __shared__ float s_al[128];
    if (threadIdx.x < 128) s_al[threadIdx.x] = g_score[b * TT + t0 + threadIdx.x];
    __syncthreads();
    float acc = 0.f;
    const float* e = enc + ((size_t)b * TT + t0) * HH + h;
    #pragma unroll 16
    for (int t = 0; t < 128; ++t) acc += s_al[t] * e[(size_t)t * HH];
    g_ctx_part[tc][b * HH + h] = acc;
}

__global__ __launch_bounds__(256) void k_ctx_final(float* __restrict__ out) {
    int idx = blockIdx.x * 256 + threadIdx.x;
    float s = 0.f;
    #pragma unroll
    for (int p = 0; p < 16; ++p) s += g_ctx_part[p][idx];
    out[idx] = s;
}

// ---------------------------------------------------------------------------
extern "C" void kernel_launch(void* const* d_in, const int* in_sizes, int n_in,
                              void* d_out, int out_size) {
    const float* enc = (const float*)d_in[0];
    const float* dec = (const float*)d_in[1];
    const float* Wa  = (const float*)d_in[2];
    const float* Ua  = (const float*)d_in[3];
    const float* Va  = (const float*)d_in[4];
    float* out = (float*)d_out;

    cudaFuncSetAttribute(k_score_mma,
                         cudaFuncAttributeMaxDynamicSharedMemorySize,
                         SMEM_TOTAL);

    k_dec_proj<<<dim3(BB, 4), 256>>>(dec, Wa);
    k_score_mma<<<dim3(NBLK, BT / TM), NTHR, SMEM_TOTAL>>>(enc, Ua, Va);
    k_softmax<<<BB, 256>>>();
    k_ctx_part<<<dim3(BB, HH / 256, 16), 256>>>(enc);
    k_ctx_final<<<(BB * HH) / 256, 256>>>(out);
}

// round 12
// speedup vs baseline: 1.7248x; 1.3327x over previous
#include <cuda_runtime.h>
#include <cuda_fp16.h>
#include <cstdint>

#define BB 32
#define TT 2048
#define HH 1024
#define UU 1024
#define BT (BB*TT)

// score GEMM tiling (fp16 mainloop)
#define TM 128
#define TN 128
#define KC 32            // K per chunk (fp16 elems)
#define NCHUNK (HH/KC)   // 32
#define NBLK (UU/TN)     // 8
#define STAGES 4

// fp16 SMEM: 32 fp16 = 64B data per row, pitch 80B -> banks (20g+tc)%32 distinct
#define PITCHB 80
#define ABYTES (TM*PITCHB)          // 10240
#define BBYTES (TN*PITCHB)          // 10240
#define BUFBYTES (ABYTES+BBYTES)    // 20480
#define SM_DEC (STAGES*BUFBYTES)    // 81920
#define SM_VA  (SM_DEC + TN*4)
#define SM_RED (SM_VA + TN*4)
#define SMEM_TOTAL (SM_RED + TM*4*4)   // 84992

// Scratch
__device__ __half g_enc16[(size_t)BT*HH];   // fp16 copy of enc (128MB)
__device__ __half g_UaT16[(size_t)UU*HH];   // Ua transposed to [u][k], fp16
__device__ float g_dec_proj[BB*UU];
__device__ float g_score_part[NBLK][BT];
__device__ float g_score[BT];
__device__ float g_ctx_part[16][BB*HH];

__device__ __forceinline__ float tanh_fast(float x) {
    float y; asm("tanh.approx.f32 %0, %1;" : "=f"(y) : "f"(x)); return y;
}
__device__ __forceinline__ uint32_t smem_u32(const void* p) {
    uint32_t a;
    asm("{ .reg .u64 t; cvta.to.shared.u64 t, %1; cvt.u32.u64 %0, t; }" : "=r"(a) : "l"(p));
    return a;
}
__device__ __forceinline__ void cpasync16(uint32_t dst, const void* src) {
    asm volatile("cp.async.cg.shared.global [%0], [%1], 16;" :: "r"(dst), "l"(src));
}
__device__ __forceinline__ void mma_f16(float* d, const uint32_t* a,
                                        uint32_t b0, uint32_t b1) {
    asm volatile(
        "mma.sync.aligned.m16n8k16.row.col.f32.f16.f16.f32 "
        "{%0,%1,%2,%3}, {%4,%5,%6,%7}, {%8,%9}, {%0,%1,%2,%3};"
        : "+f"(d[0]), "+f"(d[1]), "+f"(d[2]), "+f"(d[3])
        : "r"(a[0]), "r"(a[1]), "r"(a[2]), "r"(a[3]), "r"(b0), "r"(b1));
}

// ---------------------------------------------------------------------------
// enc fp32 -> fp16 streaming convert. grid 65536 x 256, one float4/thread.
// ---------------------------------------------------------------------------
__global__ __launch_bounds__(256) void k_split_enc(const float* __restrict__ enc) {
    size_t i = (size_t)blockIdx.x * 256 + threadIdx.x;   // over BT*HH/4
    float4 v = ((const float4*)enc)[i];
    __half2* o = (__half2*)g_enc16;
    o[2*i]   = __floats2half2_rn(v.x, v.y);
    o[2*i+1] = __floats2half2_rn(v.z, v.w);
}

// ---------------------------------------------------------------------------
// Ua[k][u] fp32 -> g_UaT16[u][k] fp16.  grid (32,32), 256 thr.
// ---------------------------------------------------------------------------
__global__ __launch_bounds__(256) void k_trans16(const float* __restrict__ Ua) {
    __shared__ float t[32][33];
    int bu = blockIdx.x * 32, bk = blockIdx.y * 32;
    int tx = threadIdx.x & 31, ty = threadIdx.x >> 5;
    #pragma unroll
    for (int i = 0; i < 32; i += 8)
        t[ty + i][tx] = Ua[(size_t)(bk + ty + i) * UU + bu + tx];
    __syncthreads();
    #pragma unroll
    for (int i = 0; i < 32; i += 8)
        g_UaT16[(size_t)(bu + ty + i) * HH + bk + tx] = __float2half(t[tx][ty + i]);
}

// ---------------------------------------------------------------------------
// dec_proj[b,u] = dec_hidden[b,:] @ Wa (fp32).  grid (B, 4), 256 thr.
// ---------------------------------------------------------------------------
__global__ __launch_bounds__(256) void k_dec_proj(const float* __restrict__ dec,
                                                  const float* __restrict__ Wa) {
    __shared__ float dh[HH];
    int b = blockIdx.x;
    int u = blockIdx.y * 256 + threadIdx.x;
    for (int i = threadIdx.x; i < HH; i += 256) dh[i] = dec[b * HH + i];
    __syncthreads();
    float acc = 0.f;
    #pragma unroll 16
    for (int h = 0; h < HH; ++h) acc += dh[h] * Wa[(size_t)h * UU + u];
    g_dec_proj[b * UU + u] = acc;
}

// ---------------------------------------------------------------------------
// Dominant kernel: fp16 mma.sync m16n8k16 GEMM with fused tanh/Va epilogue.
// 4-stage cp.async pipeline, 2 CTA/SM.
// grid = (NBLK=8, BT/TM=512), block = 256 (8 warps of 64x32 tiles).
// ---------------------------------------------------------------------------
__global__ void __launch_bounds__(256, 2)
k_score_mma(const float* __restrict__ Va) {
    extern __shared__ __align__(16) char smem[];
    const uint32_t sb = smem_u32(smem);
    const int tid  = threadIdx.x;
    const int lane = tid & 31;
    const int wid  = tid >> 5;
    const int g    = lane >> 2;       // groupID
    const int tc   = lane & 3;        // threadID_in_group
    const int Mw   = wid & 1;         // warp M row (0/1)
    const int Nw   = wid >> 1;        // warp N col (0..3)

    const int u0 = blockIdx.x * TN;
    const int r0 = blockIdx.y * TM;
    const int b  = blockIdx.y >> 4;   // r0 / TT

    float* s_dec = (float*)(smem + SM_DEC);
    float* s_va  = (float*)(smem + SM_VA);
    float* s_red = (float*)(smem + SM_RED);
    if (tid < TN) {
        s_dec[tid] = g_dec_proj[b * UU + u0 + tid];
        s_va[tid]  = Va[u0 + tid];
    }

    const __half* Ag = g_enc16 + (size_t)r0 * HH;
    const __half* Bg = g_UaT16 + (size_t)u0 * HH;

    // staging: 512 granules (16B = 8 fp16) per tile, 2 per thread
    const int st_row = tid >> 2, st_g = tid & 3;   // rows 0..63 (+64 for j=1)

    float d[4][4][4] = {};   // [Mtile][Ntile][reg]

    // ---- prologue: stage chunks 0..STAGES-2 ----
    #pragma unroll
    for (int st = 0; st < STAGES - 1; ++st) {
        const uint32_t ab = sb + st * BUFBYTES;
        const int k0 = st * KC;
        #pragma unroll
        for (int j = 0; j < 2; ++j) {
            int row = st_row + 64 * j;
            cpasync16(ab + row * PITCHB + st_g * 16,
                      Ag + (size_t)row * HH + k0 + st_g * 8);
            cpasync16(ab + ABYTES + row * PITCHB + st_g * 16,
                      Bg + (size_t)row * HH + k0 + st_g * 8);
        }
        asm volatile("cp.async.commit_group;" ::: "memory");
    }

    // per-lane fragment base offsets (bytes, within a buffer)
    const uint32_t aLane = (uint32_t)((Mw * 64 + g) * PITCHB + tc * 4);
    const uint32_t bLane = (uint32_t)((Nw * 32 + g) * PITCHB + tc * 4);

    int cur = 0, nxt = STAGES - 1;
    for (int c = 0; c < NCHUNK; ++c) {
        if (c + 1 < NCHUNK)
            asm volatile("cp.async.wait_group 2;" ::: "memory");
        else
            asm volatile("cp.async.wait_group 0;" ::: "memory");
        __syncthreads();

        // issue stage c+STAGES-1 (buffer last read in chunk c-1; safe after sync)
        if (c + STAGES - 1 < NCHUNK) {
            const uint32_t ab = sb + nxt * BUFBYTES;
            const int k0 = (c + STAGES - 1) * KC;
            #pragma unroll
            for (int j = 0; j < 2; ++j) {
                int row = st_row + 64 * j;
                cpasync16(ab + row * PITCHB + st_g * 16,
                          Ag + (size_t)row * HH + k0 + st_g * 8);
                cpasync16(ab + ABYTES + row * PITCHB + st_g * 16,
                          Bg + (size_t)row * HH + k0 + st_g * 8);
            }
            asm volatile("cp.async.commit_group;" ::: "memory");
        }

        // ---- compute chunk c from buffer cur: 2 K-steps of 16 ----
        const uint32_t bufo = cur * BUFBYTES;
        #pragma unroll
        for (int s = 0; s < 2; ++s) {
            uint32_t a[4][4];
            #pragma unroll
            for (int i = 0; i < 4; ++i) {
                const char* p = smem + bufo + aLane + i * 16 * PITCHB + s * 32;
                a[i][0] = *(const uint32_t*)(p);
                a[i][1] = *(const uint32_t*)(p + 8 * PITCHB);
                a[i][2] = *(const uint32_t*)(p + 16);
                a[i][3] = *(const uint32_t*)(p + 8 * PITCHB + 16);
            }
            #pragma unroll
            for (int jn = 0; jn < 4; ++jn) {
                const char* q = smem + bufo + ABYTES + bLane
                              + jn * 8 * PITCHB + s * 32;
                uint32_t b0 = *(const uint32_t*)(q);
                uint32_t b1 = *(const uint32_t*)(q + 16);
                #pragma unroll
                for (int i = 0; i < 4; ++i)
                    mma_f16(d[i][jn], a[i], b0, b1);
            }
        }
        cur = (cur == STAGES - 1) ? 0 : cur + 1;
        nxt = (nxt == STAGES - 1) ? 0 : nxt + 1;
    }

    // ---- fused epilogue: tanh(d + dec)*Va, reduce over u ----
    float rowacc[4][2] = {};
    #pragma unroll
    for (int i = 0; i < 4; ++i)
        #pragma unroll
        for (int jn = 0; jn < 4; ++jn)
            #pragma unroll
            for (int r = 0; r < 4; ++r) {
                int ul = Nw * 32 + jn * 8 + tc * 2 + (r & 1);
                float v = tanh_fast(d[i][jn][r] + s_dec[ul]) * s_va[ul];
                rowacc[i][r >> 1] += v;
            }
    #pragma unroll
    for (int i = 0; i < 4; ++i)
        #pragma unroll
        for (int h = 0; h < 2; ++h) {
            float v = rowacc[i][h];
            v += __shfl_xor_sync(0xffffffffu, v, 1);
            v += __shfl_xor_sync(0xffffffffu, v, 2);
            rowacc[i][h] = v;
        }
    if (tc == 0) {
        #pragma unroll
        for (int i = 0; i < 4; ++i)
            #pragma unroll
            for (int h = 0; h < 2; ++h) {
                int m = Mw * 64 + i * 16 + h * 8 + g;
                s_red[m * 4 + Nw] = rowacc[i][h];
            }
    }
    __syncthreads();
    if (tid < TM) {
        float s = s_red[tid * 4] + s_red[tid * 4 + 1]
                + s_red[tid * 4 + 2] + s_red[tid * 4 + 3];
        g_score_part[blockIdx.x][r0 + tid] = s;
    }
}

// ---------------------------------------------------------------------------
// Softmax over T (sums the 8 N-block partials). grid (B), 256 thr.
// ---------------------------------------------------------------------------
__global__ __launch_bounds__(256) void k_softmax() {
    int b = blockIdx.x, tid = threadIdx.x;
    __shared__ float sm[256];
    float* sc = g_score + b * TT;

    float m = -1e30f;
    for (int t = tid; t < TT; t += 256) {
        float v = 0.f;
        #pragma unroll
        for (int p = 0; p < NBLK; ++p) v += g_score_part[p][b * TT + t];
        sc[t] = v;
        m = fmaxf(m, v);
    }
    sm[tid] = m; __syncthreads();
    for (int s = 128; s > 0; s >>= 1) {
        if (tid < s) sm[tid] = fmaxf(sm[tid], sm[tid + s]);
        __syncthreads();
    }
    m = sm[0]; __syncthreads();

    float sum = 0.f;
    for (int t = tid; t < TT; t += 256) {
        float e = __expf(sc[t] - m);
        sc[t] = e; sum += e;
    }
    sm[tid] = sum; __syncthreads();
    for (int s = 128; s > 0; s >>= 1) {
        if (tid < s) sm[tid] += sm[tid + s];
        __syncthreads();
    }
    float inv = 1.f / sm[0];
    for (int t = tid; t < TT; t += 256) sc[t] *= inv;
}

// ---------------------------------------------------------------------------
// Context: grid (B, H/256, 16), block 256. Each block: 128 t's for 256 h's.
// ---------------------------------------------------------------------------
__global__ __launch_bounds__(256) void k_ctx_part(const float* __restrict__ enc) {
    int b = blockIdx.x, hc = blockIdx.y, tc = blockIdx.z;
    int h = hc * 256 + threadIdx.x;
    int t0 = tc * 128;
    __shared__ float s_al[128];
    if (threadIdx.x < 128) s_al[threadIdx.x] = g_score[b * TT + t0 + threadIdx.x];
    __syncthreads();
    float acc = 0.f;
    const float* e = enc + ((size_t)b * TT + t0) * HH + h;
    #pragma unroll 16
    for (int t = 0; t < 128; ++t) acc += s_al[t] * e[(size_t)t * HH];
    g_ctx_part[tc][b * HH + h] = acc;
}

__global__ __launch_bounds__(256) void k_ctx_final(float* __restrict__ out) {
    int idx = blockIdx.x * 256 + threadIdx.x;
    float s = 0.f;
    #pragma unroll
    for (int p = 0; p < 16; ++p) s += g_ctx_part[p][idx];
    out[idx] = s;
}

// ---------------------------------------------------------------------------
extern "C" void kernel_launch(void* const* d_in, const int* in_sizes, int n_in,
                              void* d_out, int out_size) {
    const float* enc = (const float*)d_in[0];
    const float* dec = (const float*)d_in[1];
    const float* Wa  = (const float*)d_in[2];
    const float* Ua  = (const float*)d_in[3];
    const float* Va  = (const float*)d_in[4];
    float* out = (float*)d_out;

    cudaFuncSetAttribute(k_score_mma,
                         cudaFuncAttributeMaxDynamicSharedMemorySize,
                         SMEM_TOTAL);

    k_split_enc<<<(BT * (HH / 4)) / 256, 256>>>(enc);
    k_trans16<<<dim3(UU / 32, HH / 32), 256>>>(Ua);
    k_dec_proj<<<dim3(BB, 4), 256>>>(dec, Wa);
    k_score_mma<<<dim3(NBLK, BT / TM), 256, SMEM_TOTAL>>>(Va);
    k_softmax<<<BB, 256>>>();
    k_ctx_part<<<dim3(BB, HH / 256, 16), 256>>>(enc);
    k_ctx_final<<<(BB * HH) / 256, 256>>>(out);
}

// round 13
// speedup vs baseline: 3.0220x; 1.7521x over previous
#include <cuda_runtime.h>
#include <cuda_fp16.h>
#include <cstdint>

#define BB 32
#define TT 2048
#define HH 1024
#define UU 1024
#define BT (BB*TT)

// score GEMM tiling (fp16 mainloop)
#define TM 128
#define TN 128
#define KC 64            // K per chunk (fp16 elems) = 128B per row
#define NCHUNK (HH/KC)   // 16
#define NBLK (UU/TN)     // 8
#define STAGES 3

// SMEM: 64 fp16 = 128B data per row + 16B pad -> pitch 144B
// frag LDS banks: word = (36*g + tc) % 32 = (4g + tc) % 32, all 32 distinct
#define PITCHB 144
#define TILEB (128*PITCHB)          // 18432
#define BUFBYTES (2*TILEB)          // 36864
#define SMEM_TOTAL (STAGES*BUFBYTES)   // 110592  (s_red aliases buffer 0)

// Scratch
__device__ __half g_enc16[(size_t)BT*HH];   // fp16 copy of enc (128MB)
__device__ __half g_UaT16[(size_t)UU*HH];   // Ua transposed to [u][k], fp16
__device__ float g_dec_proj[BB*UU];
__device__ float g_score_part[NBLK][BT];
__device__ float g_score[BT];
__device__ float g_ctx_part[16][BB*HH];

__device__ __forceinline__ float tanh_fast(float x) {
    float y; asm("tanh.approx.f32 %0, %1;" : "=f"(y) : "f"(x)); return y;
}
__device__ __forceinline__ uint32_t smem_u32(const void* p) {
    uint32_t a;
    asm("{ .reg .u64 t; cvta.to.shared.u64 t, %1; cvt.u32.u64 %0, t; }" : "=r"(a) : "l"(p));
    return a;
}
__device__ __forceinline__ void cpasync16(uint32_t dst, const void* src) {
    asm volatile("cp.async.cg.shared.global [%0], [%1], 16;" :: "r"(dst), "l"(src));
}
__device__ __forceinline__ void mma_f16(float* d, const uint32_t* a,
                                        uint32_t b0, uint32_t b1) {
    asm volatile(
        "mma.sync.aligned.m16n8k16.row.col.f32.f16.f16.f32 "
        "{%0,%1,%2,%3}, {%4,%5,%6,%7}, {%8,%9}, {%0,%1,%2,%3};"
        : "+f"(d[0]), "+f"(d[1]), "+f"(d[2]), "+f"(d[3])
        : "r"(a[0]), "r"(a[1]), "r"(a[2]), "r"(a[3]), "r"(b0), "r"(b1));
}

// ---------------------------------------------------------------------------
// Fused prep: [0,128) dec_proj | [128,1152) Ua transpose | [1152,...) enc->fp16
// ---------------------------------------------------------------------------
__global__ __launch_bounds__(256) void k_prep(const float* __restrict__ enc,
                                              const float* __restrict__ dec,
                                              const float* __restrict__ Wa,
                                              const float* __restrict__ Ua) {
    __shared__ float sh[1056];
    const int bid = blockIdx.x;
    const int tid = threadIdx.x;

    if (bid < 128) {
        // dec_proj[b,u] = dec_hidden[b,:] @ Wa
        int b = bid >> 2;
        int u = (bid & 3) * 256 + tid;
        for (int i = tid; i < HH; i += 256) sh[i] = dec[b * HH + i];
        __syncthreads();
        float acc = 0.f;
        #pragma unroll 16
        for (int h = 0; h < HH; ++h) acc += sh[h] * Wa[(size_t)h * UU + u];
        g_dec_proj[b * UU + u] = acc;
    } else if (bid < 1152) {
        // Ua[k][u] -> g_UaT16[u][k] (fp16)
        float (*t)[33] = (float(*)[33])sh;
        int q = bid - 128;
        int bu = (q & 31) * 32, bk = (q >> 5) * 32;
        int tx = tid & 31, ty = tid >> 5;
        #pragma unroll
        for (int i = 0; i < 32; i += 8)
            t[ty + i][tx] = Ua[(size_t)(bk + ty + i) * UU + bu + tx];
        __syncthreads();
        #pragma unroll
        for (int i = 0; i < 32; i += 8)
            g_UaT16[(size_t)(bu + ty + i) * HH + bk + tx] = __float2half(t[tx][ty + i]);
    } else {
        // enc fp32 -> fp16 (one float4 per thread)
        size_t i = (size_t)(bid - 1152) * 256 + tid;
        float4 v = ((const float4*)enc)[i];
        __half2* o = (__half2*)g_enc16;
        o[2*i]   = __floats2half2_rn(v.x, v.y);
        o[2*i+1] = __floats2half2_rn(v.z, v.w);
    }
}

// ---------------------------------------------------------------------------
// Dominant kernel: fp16 mma.sync m16n8k16 GEMM with fused tanh/Va epilogue.
// KC=64 chunks, 3-stage cp.async pipeline, 2 CTA/SM.
// grid = (NBLK=8, BT/TM=512), block = 256 (8 warps of 64x32 tiles).
// ---------------------------------------------------------------------------
__global__ void __launch_bounds__(256, 2)
k_score_mma(const float* __restrict__ Va) {
    extern __shared__ __align__(16) char smem[];
    const uint32_t sb = smem_u32(smem);
    const int tid  = threadIdx.x;
    const int lane = tid & 31;
    const int wid  = tid >> 5;
    const int g    = lane >> 2;       // groupID
    const int tc   = lane & 3;        // threadID_in_group
    const int Mw   = wid & 1;         // warp M row (0/1)
    const int Nw   = wid >> 1;        // warp N col (0..3)

    const int u0 = blockIdx.x * TN;
    const int r0 = blockIdx.y * TM;
    const int b  = blockIdx.y >> 4;   // r0 / TT

    const __half* Ag = g_enc16 + (size_t)r0 * HH;
    const __half* Bg = g_UaT16 + (size_t)u0 * HH;

    // staging: 128 rows x 8 granules (16B) per tile; 4 A + 4 B per thread/stage
    const int st_row = tid >> 3, st_g = tid & 7;

    float d[4][4][4] = {};   // [Mtile][Ntile][reg]

    // ---- prologue: stage chunks 0,1 ----
    #pragma unroll
    for (int st = 0; st < STAGES - 1; ++st) {
        const uint32_t ab = sb + st * BUFBYTES;
        const int k0 = st * KC;
        #pragma unroll
        for (int j = 0; j < 4; ++j) {
            int row = st_row + 32 * j;
            cpasync16(ab + row * PITCHB + st_g * 16,
                      Ag + (size_t)row * HH + k0 + st_g * 8);
            cpasync16(ab + TILEB + row * PITCHB + st_g * 16,
                      Bg + (size_t)row * HH + k0 + st_g * 8);
        }
        asm volatile("cp.async.commit_group;" ::: "memory");
    }

    // per-lane fragment base offsets (bytes, within a buffer)
    const uint32_t aLane = (uint32_t)((Mw * 64 + g) * PITCHB + tc * 4);
    const uint32_t bLane = (uint32_t)((Nw * 32 + g) * PITCHB + tc * 4);

    int cur = 0, nxt = STAGES - 1;
    for (int c = 0; c < NCHUNK; ++c) {
        if (c + 1 < NCHUNK)
            asm volatile("cp.async.wait_group 1;" ::: "memory");
        else
            asm volatile("cp.async.wait_group 0;" ::: "memory");
        __syncthreads();

        // issue stage c+2 (buffer last read in chunk c-1; safe after sync)
        if (c + STAGES - 1 < NCHUNK) {
            const uint32_t ab = sb + nxt * BUFBYTES;
            const int k0 = (c + STAGES - 1) * KC;
            #pragma unroll
            for (int j = 0; j < 4; ++j) {
                int row = st_row + 32 * j;
                cpasync16(ab + row * PITCHB + st_g * 16,
                          Ag + (size_t)row * HH + k0 + st_g * 8);
                cpasync16(ab + TILEB + row * PITCHB + st_g * 16,
                          Bg + (size_t)row * HH + k0 + st_g * 8);
            }
            asm volatile("cp.async.commit_group;" ::: "memory");
        }

        // ---- compute chunk c from buffer cur: 4 K-steps of 16 ----
        const uint32_t bufo = cur * BUFBYTES;
        #pragma unroll
        for (int s = 0; s < 4; ++s) {
            uint32_t a[4][4];
            #pragma unroll
            for (int i = 0; i < 4; ++i) {
                const char* p = smem + bufo + aLane + i * 16 * PITCHB + s * 32;
                a[i][0] = *(const uint32_t*)(p);
                a[i][1] = *(const uint32_t*)(p + 8 * PITCHB);
                a[i][2] = *(const uint32_t*)(p + 16);
                a[i][3] = *(const uint32_t*)(p + 8 * PITCHB + 16);
            }
            #pragma unroll
            for (int jn = 0; jn < 4; ++jn) {
                const char* q = smem + bufo + TILEB + bLane
                              + jn * 8 * PITCHB + s * 32;
                uint32_t b0 = *(const uint32_t*)(q);
                uint32_t b1 = *(const uint32_t*)(q + 16);
                #pragma unroll
                for (int i = 0; i < 4; ++i)
                    mma_f16(d[i][jn], a[i], b0, b1);
            }
        }
        cur = (cur == STAGES - 1) ? 0 : cur + 1;
        nxt = (nxt == STAGES - 1) ? 0 : nxt + 1;
    }

    // ---- fused epilogue: tanh(d + dec)*Va, reduce over u ----
    // dec/Va fetched from GMEM post-loop (cached; off the mainloop critical path)
    float vdec[4][2], vva[4][2];
    #pragma unroll
    for (int jn = 0; jn < 4; ++jn)
        #pragma unroll
        for (int rr = 0; rr < 2; ++rr) {
            int ul = Nw * 32 + jn * 8 + tc * 2 + rr;
            vdec[jn][rr] = g_dec_proj[b * UU + u0 + ul];
            vva[jn][rr]  = Va[u0 + ul];
        }

    float rowacc[4][2] = {};
    #pragma unroll
    for (int i = 0; i < 4; ++i)
        #pragma unroll
        for (int jn = 0; jn < 4; ++jn)
            #pragma unroll
            for (int r = 0; r < 4; ++r) {
                float v = tanh_fast(d[i][jn][r] + vdec[jn][r & 1]) * vva[jn][r & 1];
                rowacc[i][r >> 1] += v;
            }
    #pragma unroll
    for (int i = 0; i < 4; ++i)
        #pragma unroll
        for (int h = 0; h < 2; ++h) {
            float v = rowacc[i][h];
            v += __shfl_xor_sync(0xffffffffu, v, 1);
            v += __shfl_xor_sync(0xffffffffu, v, 2);
            rowacc[i][h] = v;
        }

    // s_red aliases stage buffer 0 — wait for all warps to finish the mainloop
    __syncthreads();
    float* s_red = (float*)smem;
    if (tc == 0) {
        #pragma unroll
        for (int i = 0; i < 4; ++i)
            #pragma unroll
            for (int h = 0; h < 2; ++h) {
                int m = Mw * 64 + i * 16 + h * 8 + g;
                s_red[m * 4 + Nw] = rowacc[i][h];
            }
    }
    __syncthreads();
    if (tid < TM) {
        float s = s_red[tid * 4] + s_red[tid * 4 + 1]
                + s_red[tid * 4 + 2] + s_red[tid * 4 + 3];
        g_score_part[blockIdx.x][r0 + tid] = s;
    }
}

// ---------------------------------------------------------------------------
// Softmax over T (sums the 8 N-block partials). grid (B), 256 thr.
// ---------------------------------------------------------------------------
__global__ __launch_bounds__(256) void k_softmax() {
    int b = blockIdx.x, tid = threadIdx.x;
    __shared__ float sm[256];
    float* sc = g_score + b * TT;

    float m = -1e30f;
    for (int t = tid; t < TT; t += 256) {
        float v = 0.f;
        #pragma unroll
        for (int p = 0; p < NBLK; ++p) v += g_score_part[p][b * TT + t];
        sc[t] = v;
        m = fmaxf(m, v);
    }
    sm[tid] = m; __syncthreads();
    for (int s = 128; s > 0; s >>= 1) {
        if (tid < s) sm[tid] = fmaxf(sm[tid], sm[tid + s]);
        __syncthreads();
    }
    m = sm[0]; __syncthreads();

    float sum = 0.f;
    for (int t = tid; t < TT; t += 256) {
        float e = __expf(sc[t] - m);
        sc[t] = e; sum += e;
    }
    sm[tid] = sum; __syncthreads();
    for (int s = 128; s > 0; s >>= 1) {
        if (tid < s) sm[tid] += sm[tid + s];
        __syncthreads();
    }
    float inv = 1.f / sm[0];
    for (int t = tid; t < TT; t += 256) sc[t] *= inv;
}

// ---------------------------------------------------------------------------
// Context from fp16 enc: grid (B, 2, 16), block 256.
// Each block: 128 t's for 512 h's (half2 per thread).
// ---------------------------------------------------------------------------
__global__ __launch_bounds__(256) void k_ctx_part() {
    int b = blockIdx.x, hc = blockIdx.y, tc = blockIdx.z;
    int t0 = tc * 128;
    __shared__ float s_al[128];
    if (threadIdx.x < 128) s_al[threadIdx.x] = g_score[b * TT + t0 + threadIdx.x];
    __syncthreads();

    const __half2* e = (const __half2*)g_enc16
                     + ((size_t)b * TT + t0) * (HH/2) + hc * 256 + threadIdx.x;
    float ax = 0.f, ay = 0.f;
    #pragma unroll 16
    for (int t = 0; t < 128; ++t) {
        float2 f = __half22float2(e[(size_t)t * (HH/2)]);
        ax += s_al[t] * f.x;
        ay += s_al[t] * f.y;
    }
    int h2 = hc * 256 + threadIdx.x;
    ((float2*)&g_ctx_part[tc][b * HH])[h2] = make_float2(ax, ay);
}

__global__ __launch_bounds__(256) void k_ctx_final(float* __restrict__ out) {
    int idx = blockIdx.x * 256 + threadIdx.x;
    float s = 0.f;
    #pragma unroll
    for (int p = 0; p < 16; ++p) s += g_ctx_part[p][idx];
    out[idx] = s;
}

// ---------------------------------------------------------------------------
extern "C" void kernel_launch(void* const* d_in, const int* in_sizes, int n_in,
                              void* d_out, int out_size) {
    const float* enc = (const float*)d_in[0];
    const float* dec = (const float*)d_in[1];
    const float* Wa  = (const float*)d_in[2];
    const float* Ua  = (const float*)d_in[3];
    const float* Va  = (const float*)d_in[4];
    float* out = (float*)d_out;

    cudaFuncSetAttribute(k_score_mma,
                         cudaFuncAttributeMaxDynamicSharedMemorySize,
                         SMEM_TOTAL);

    k_prep<<<1152 + (BT * (HH / 4)) / 256, 256>>>(enc, dec, Wa, Ua);
    k_score_mma<<<dim3(NBLK, BT / TM), 256, SMEM_TOTAL>>>(Va);
    k_softmax<<<BB, 256>>>();
    k_ctx_part<<<dim3(BB, 2, 16), 256>>>();
    k_ctx_final<<<(BB * HH) / 256, 256>>>(out);
}